// round 4
// baseline (speedup 1.0000x reference)
#include <cuda_runtime.h>
#include <math.h>

// Problem constants
#define QLEN 512
#define RLEN 1024
#define BSZ  8
#define NHEAD 16
#define DHEAD 64
#define DMODEL 1024
#define QB (QLEN*BSZ)          // 4096
#define RB (RLEN*BSZ)          // 8192
#define BN_TOT (BSZ*NHEAD)     // 128
#define IJ (QLEN*QLEN)         // 262144
#define ATT_SCALE 0.125f       // 1/sqrt(64)

// ---------------- scratch (static device globals; no allocation) -------------
__device__ float g_k  [QB*DMODEL];
__device__ float g_v  [QB*DMODEL];
__device__ float g_kr [RB*DMODEL];
__device__ float g_q  [QB*DMODEL];
__device__ float g_av [QB*DMODEL];
__device__ float g_tmp[QB*DMODEL];
__device__ float g_kbw[BN_TOT*QLEN];
__device__ float g_krb[BN_TOT*RLEN];
__device__ float g_e0 [QLEN*BN_TOT];
__device__ float g_e1 [QLEN*BN_TOT];
__device__ float g_S1 [(size_t)BN_TOT*QLEN*QLEN];   // also reused as P
__device__ float g_S2 [(size_t)BN_TOT*QLEN*RLEN];
__device__ float g_maskTh[(size_t)BN_TOT*IJ];
__device__ float g_maskTg[(size_t)BN_TOT*IJ];
__device__ float g_segT[16*IJ];

// ---------------- warp reduction helpers -------------------------------------
__device__ __forceinline__ float warpMax(float v) {
    #pragma unroll
    for (int o = 16; o > 0; o >>= 1) v = fmaxf(v, __shfl_xor_sync(0xffffffffu, v, o));
    return v;
}
__device__ __forceinline__ float warpSum(float v) {
    #pragma unroll
    for (int o = 16; o > 0; o >>= 1) v += __shfl_xor_sync(0xffffffffu, v, o);
    return v;
}

// ---------------- batched tiled SGEMM: C = A(MxK) * B(KxN), row-major --------
// BM=BN=64, BK=16, 256 threads, 4x4 per thread, register-prefetched k-loop.
// All dims assumed multiples of tile sizes (true for every call below).
__global__ void __launch_bounds__(256, 3)
sgemm_nn(const float* __restrict__ A, const float* __restrict__ B,
         float* __restrict__ C,
         int K, int lda, int ldb, int ldc,
         long long sA, long long sB, long long sC)
{
    __shared__ float As[16][64];
    __shared__ float Bs[16][64];
    const int bz = blockIdx.z;
    A += (size_t)bz * sA; B += (size_t)bz * sB; C += (size_t)bz * sC;
    const int m0 = blockIdx.y * 64, n0 = blockIdx.x * 64;
    const int tid = threadIdx.x;
    const int tx = tid & 15, ty = tid >> 4;
    const int arow = tid >> 2, acol = (tid & 3) * 4;   // A: 64 rows x 16 k
    const int brow = tid >> 4, bcol = (tid & 15) * 4;  // B: 16 k x 64 cols
    float acc[4][4] = {};

    const float* aptr = A + (size_t)(m0 + arow) * lda + acol;
    const float* bptr = B + (size_t)brow * ldb + n0 + bcol;

    float4 av = *(const float4*)(aptr);
    float4 bv = *(const float4*)(bptr);

    for (int kt = 0; kt < K; kt += 16) {
        As[acol + 0][arow] = av.x; As[acol + 1][arow] = av.y;
        As[acol + 2][arow] = av.z; As[acol + 3][arow] = av.w;
        *(float4*)&Bs[brow][bcol] = bv;
        __syncthreads();
        if (kt + 16 < K) {                       // prefetch next k-tile
            av = *(const float4*)(aptr + kt + 16);
            bv = *(const float4*)(bptr + (size_t)(kt + 16) * ldb);
        }
        #pragma unroll
        for (int k = 0; k < 16; ++k) {
            float4 a = *(const float4*)&As[k][ty * 4];
            float4 b = *(const float4*)&Bs[k][tx * 4];
            acc[0][0] += a.x*b.x; acc[0][1] += a.x*b.y; acc[0][2] += a.x*b.z; acc[0][3] += a.x*b.w;
            acc[1][0] += a.y*b.x; acc[1][1] += a.y*b.y; acc[1][2] += a.y*b.z; acc[1][3] += a.y*b.w;
            acc[2][0] += a.z*b.x; acc[2][1] += a.z*b.y; acc[2][2] += a.z*b.z; acc[2][3] += a.z*b.w;
            acc[3][0] += a.w*b.x; acc[3][1] += a.w*b.y; acc[3][2] += a.w*b.z; acc[3][3] += a.w*b.w;
        }
        __syncthreads();
    }
    #pragma unroll
    for (int r = 0; r < 4; ++r) {
        float4 o = make_float4(acc[r][0], acc[r][1], acc[r][2], acc[r][3]);
        *(float4*)(C + (size_t)(m0 + ty * 4 + r) * ldc + n0 + tx * 4) = o;
    }
}

// ---------------- batched tiled SGEMM NT: C = A(MxK) * B(NxK)^T --------------
__global__ void __launch_bounds__(256, 3)
sgemm_nt(const float* __restrict__ A, const float* __restrict__ B,
         float* __restrict__ C,
         int K, int lda, int ldb, int ldc,
         long long sA, long long sB, long long sC)
{
    __shared__ float As[16][64];
    __shared__ float Bs[16][64];
    const int bz = blockIdx.z;
    A += (size_t)bz * sA; B += (size_t)bz * sB; C += (size_t)bz * sC;
    const int m0 = blockIdx.y * 64, n0 = blockIdx.x * 64;
    const int tid = threadIdx.x;
    const int tx = tid & 15, ty = tid >> 4;
    const int row = tid >> 2, kcol = (tid & 3) * 4;  // 64 rows x 16 k (A and B)
    float acc[4][4] = {};

    const float* aptr = A + (size_t)(m0 + row) * lda + kcol;
    const float* bptr = B + (size_t)(n0 + row) * ldb + kcol;

    float4 av = *(const float4*)(aptr);
    float4 bv = *(const float4*)(bptr);

    for (int kt = 0; kt < K; kt += 16) {
        As[kcol + 0][row] = av.x; As[kcol + 1][row] = av.y;
        As[kcol + 2][row] = av.z; As[kcol + 3][row] = av.w;
        Bs[kcol + 0][row] = bv.x; Bs[kcol + 1][row] = bv.y;
        Bs[kcol + 2][row] = bv.z; Bs[kcol + 3][row] = bv.w;
        __syncthreads();
        if (kt + 16 < K) {                       // prefetch next k-tile
            av = *(const float4*)(aptr + kt + 16);
            bv = *(const float4*)(bptr + kt + 16);
        }
        #pragma unroll
        for (int k = 0; k < 16; ++k) {
            float4 a = *(const float4*)&As[k][ty * 4];
            float4 b = *(const float4*)&Bs[k][tx * 4];
            acc[0][0] += a.x*b.x; acc[0][1] += a.x*b.y; acc[0][2] += a.x*b.z; acc[0][3] += a.x*b.w;
            acc[1][0] += a.y*b.x; acc[1][1] += a.y*b.y; acc[1][2] += a.y*b.z; acc[1][3] += a.y*b.w;
            acc[2][0] += a.z*b.x; acc[2][1] += a.z*b.y; acc[2][2] += a.z*b.z; acc[2][3] += a.z*b.w;
            acc[3][0] += a.w*b.x; acc[3][1] += a.w*b.y; acc[3][2] += a.w*b.z; acc[3][3] += a.w*b.w;
        }
        __syncthreads();
    }
    #pragma unroll
    for (int r = 0; r < 4; ++r) {
        float4 o = make_float4(acc[r][0], acc[r][1], acc[r][2], acc[r][3]);
        *(float4*)(C + (size_t)(m0 + ty * 4 + r) * ldc + n0 + tx * 4) = o;
    }
}

// ---------------- 2D transpose: in[R][C] -> out[C][R] -----------------------
__global__ void transpose2d(const float* __restrict__ in, float* __restrict__ out,
                            int R, int C)
{
    __shared__ float tile[32][33];
    const int c0 = blockIdx.x * 32, r0 = blockIdx.y * 32;
    for (int rr = threadIdx.y; rr < 32; rr += 8) {
        int r = r0 + rr, c = c0 + threadIdx.x;
        if (r < R && c < C) tile[rr][threadIdx.x] = in[(size_t)r * C + c];
    }
    __syncthreads();
    for (int cc = threadIdx.y; cc < 32; cc += 8) {
        int oc = c0 + cc, orw = r0 + threadIdx.x;
        if (oc < C && orw < R) out[(size_t)oc * R + orw] = tile[threadIdx.x][cc];
    }
}

// ---------------- kbw / krb: out[bn*J + j] = bias[n] . vecs[j,b,n,:] ---------
__global__ void bias_dot(const float* __restrict__ vecs, const float* __restrict__ bias,
                         float* __restrict__ out, int J)
{
    int idx = blockIdx.x * blockDim.x + threadIdx.x;
    if (idx >= BN_TOT * J) return;
    int bn = idx / J, j = idx - bn * J;
    int n = bn & 15;
    const float4* v = (const float4*)(vecs + ((size_t)j * BN_TOT + bn) * DHEAD);
    const float4* bp = (const float4*)(bias + n * DHEAD);
    float acc = 0.f;
    #pragma unroll
    for (int d = 0; d < 16; ++d) {
        float4 a = v[d], b = bp[d];
        acc += a.x*b.x + a.y*b.y + a.z*b.z + a.w*b.w;
    }
    out[idx] = acc;
}

// ---------------- efq[i,b,n,s] = (q+r_s_bias) . seg_embed[s,n,:] -------------
__global__ void compute_efq(const float* __restrict__ q, const float* __restrict__ rsb,
                            const float* __restrict__ se,
                            float* __restrict__ e0, float* __restrict__ e1)
{
    int idx = blockIdx.x * blockDim.x + threadIdx.x;   // (i*8+b)*16+n, 65536 total
    if (idx >= QLEN * BN_TOT) return;
    int n = idx & 15;
    const float* qp = q + (size_t)idx * DHEAD;
    const float* rb = rsb + n * DHEAD;
    const float* s0 = se + n * DHEAD;
    const float* s1 = se + (16 + n) * DHEAD;
    float a0 = 0.f, a1 = 0.f;
    #pragma unroll
    for (int d = 0; d < DHEAD; ++d) {
        float qv = qp[d] + rb[d];
        a0 += qv * s0[d];
        a1 += qv * s1[d];
    }
    e0[idx] = a0; e1[idx] = a1;
}

// ---------------- combine scores + softmax; writes P in place over S1 -------
__global__ void __launch_bounds__(256, 4)
combine_softmax(float* __restrict__ S1, const float* __restrict__ S2,
                const float* __restrict__ kbw, const float* __restrict__ krb,
                const float* __restrict__ e0a, const float* __restrict__ e1a,
                const float* __restrict__ maskT, const float* __restrict__ segT)
{
    const int i = blockIdx.x, bn = blockIdx.y, b = bn >> 4;
    const int tid = threadIdx.x;                 // 256 threads, 2 j each
    float* s1row = S1 + ((size_t)bn * QLEN + i) * QLEN;
    const float* s2row = S2 + ((size_t)bn * QLEN + i) * RLEN;
    const float* mrow  = maskT + (size_t)bn * IJ + (size_t)i * QLEN;
    const float* sg0   = segT + (size_t)(b * 2) * IJ + (size_t)i * QLEN;
    const float* sg1   = sg0 + IJ;
    const float* kb = kbw + bn * QLEN;
    const float* kr = krb + bn * RLEN;
    const float e0 = e0a[i * BN_TOT + bn], e1 = e1a[i * BN_TOT + bn];

    float sc[2];
    #pragma unroll
    for (int t = 0; t < 2; ++t) {
        int j = tid + t * 256;
        int p = QLEN - i + j;                    // rel_shift gather, in [1,1023]
        float v = s1row[j] + s2row[p] + kb[j] + kr[p] + sg0[j] * e0 + sg1[j] * e1;
        sc[t] = v * ATT_SCALE - 1e30f * mrow[j];
    }

    const int lane = tid & 31, wid = tid >> 5;
    __shared__ float sred[8];

    float mx = warpMax(fmaxf(sc[0], sc[1]));
    if (lane == 0) sred[wid] = mx;
    __syncthreads();
    if (wid == 0) {
        float v = (lane < 8) ? sred[lane] : -3.0e38f;
        v = warpMax(v);
        if (lane == 0) sred[0] = v;
    }
    __syncthreads();
    mx = sred[0];
    __syncthreads();

    float ex0 = expf(sc[0] - mx), ex1 = expf(sc[1] - mx);
    float s = warpSum(ex0 + ex1);
    if (lane == 0) sred[wid] = s;
    __syncthreads();
    if (wid == 0) {
        float v = (lane < 8) ? sred[lane] : 0.f;
        v = warpSum(v);
        if (lane == 0) sred[0] = v;
    }
    __syncthreads();
    float inv = 1.f / sred[0];
    s1row[tid]       = ex0 * inv;
    s1row[tid + 256] = ex1 * inv;
}

// ---------------- residual + LayerNorm over last dim (1024) ------------------
__global__ void __launch_bounds__(256, 4)
residual_ln(const float* __restrict__ proj, const float* __restrict__ res,
            const float* __restrict__ gamma, const float* __restrict__ beta,
            float* __restrict__ out)
{
    const int row = blockIdx.x;                  // 4096 rows
    const int tid = threadIdx.x;                 // 256 threads, 4 cols each
    const float* p = proj + (size_t)row * DMODEL;
    const float* r = res  + (size_t)row * DMODEL;
    float x[4];
    float s = 0.f;
    #pragma unroll
    for (int c = 0; c < 4; ++c) {
        int col = tid + c * 256;
        x[c] = p[col] + r[col];
        s += x[c];
    }
    const int lane = tid & 31, wid = tid >> 5;
    __shared__ float sred[8];
    s = warpSum(s);
    if (lane == 0) sred[wid] = s;
    __syncthreads();
    if (wid == 0) {
        float v = (lane < 8) ? sred[lane] : 0.f;
        v = warpSum(v);
        if (lane == 0) sred[0] = v;
    }
    __syncthreads();
    const float mu = sred[0] * (1.f / DMODEL);
    __syncthreads();
    float vs = 0.f;
    #pragma unroll
    for (int c = 0; c < 4; ++c) { float d = x[c] - mu; vs += d * d; }
    vs = warpSum(vs);
    if (lane == 0) sred[wid] = vs;
    __syncthreads();
    if (wid == 0) {
        float v = (lane < 8) ? sred[lane] : 0.f;
        v = warpSum(v);
        if (lane == 0) sred[0] = v;
    }
    __syncthreads();
    const float rs = rsqrtf(sred[0] * (1.f / DMODEL) + 1e-12f);
    float* o = out + (size_t)row * DMODEL;
    #pragma unroll
    for (int c = 0; c < 4; ++c) {
        int col = tid + c * 256;
        o[col] = (x[c] - mu) * rs * gamma[col] + beta[col];
    }
}

// ---------------- launch --------------------------------------------------
extern "C" void kernel_launch(void* const* d_in, const int* in_sizes, int n_in,
                              void* d_out, int out_size)
{
    const float* h       = (const float*)d_in[0];
    const float* g       = (const float*)d_in[1];
    const float* r       = (const float*)d_in[2];
    const float* mask_h  = (const float*)d_in[3];
    const float* mask_g  = (const float*)d_in[4];
    const float* seg_mat = (const float*)d_in[5];
    const float* wq      = (const float*)d_in[6];
    const float* wk      = (const float*)d_in[7];
    const float* wv      = (const float*)d_in[8];
    const float* wo      = (const float*)d_in[9];
    const float* wr      = (const float*)d_in[10];
    const float* rwb     = (const float*)d_in[11];
    const float* rrb     = (const float*)d_in[12];
    const float* rsb     = (const float*)d_in[13];
    const float* se      = (const float*)d_in[14];
    const float* gamma   = (const float*)d_in[15];
    const float* beta    = (const float*)d_in[16];
    float* out = (float*)d_out;

    float *pk, *pv, *pkr, *pq, *pav, *ptmp, *pkbw, *pkrb, *pe0, *pe1,
          *pS1, *pS2, *pmTh, *pmTg, *psegT;
    cudaGetSymbolAddress((void**)&pk,   g_k);
    cudaGetSymbolAddress((void**)&pv,   g_v);
    cudaGetSymbolAddress((void**)&pkr,  g_kr);
    cudaGetSymbolAddress((void**)&pq,   g_q);
    cudaGetSymbolAddress((void**)&pav,  g_av);
    cudaGetSymbolAddress((void**)&ptmp, g_tmp);
    cudaGetSymbolAddress((void**)&pkbw, g_kbw);
    cudaGetSymbolAddress((void**)&pkrb, g_krb);
    cudaGetSymbolAddress((void**)&pe0,  g_e0);
    cudaGetSymbolAddress((void**)&pe1,  g_e1);
    cudaGetSymbolAddress((void**)&pS1,  g_S1);
    cudaGetSymbolAddress((void**)&pS2,  g_S2);
    cudaGetSymbolAddress((void**)&pmTh, g_maskTh);
    cudaGetSymbolAddress((void**)&pmTg, g_maskTg);
    cudaGetSymbolAddress((void**)&psegT, g_segT);

    // ---- shared precompute ----
    // K, V projections: [4096,1024] = h[4096,1024] @ w[1024,1024]
    sgemm_nn<<<dim3(16, 64, 1), 256>>>(h, wk, pk, DMODEL, DMODEL, DMODEL, DMODEL, 0, 0, 0);
    sgemm_nn<<<dim3(16, 64, 1), 256>>>(h, wv, pv, DMODEL, DMODEL, DMODEL, DMODEL, 0, 0, 0);
    // Kr projection: [8192,1024]
    sgemm_nn<<<dim3(16, 128, 1), 256>>>(r, wr, pkr, DMODEL, DMODEL, DMODEL, DMODEL, 0, 0, 0);
    // bias . key dot products
    bias_dot<<<(BN_TOT * QLEN + 255) / 256, 256>>>(pk,  rwb, pkbw, QLEN);
    bias_dot<<<(BN_TOT * RLEN + 255) / 256, 256>>>(pkr, rrb, pkrb, RLEN);
    // transposes: [ij, bn] -> [bn, ij]
    transpose2d<<<dim3(4, IJ / 32), dim3(32, 8)>>>(mask_h,  pmTh, IJ, BN_TOT);
    transpose2d<<<dim3(4, IJ / 32), dim3(32, 8)>>>(mask_g,  pmTg, IJ, BN_TOT);
    transpose2d<<<dim3(1, IJ / 32), dim3(32, 8)>>>(seg_mat, psegT, IJ, 16);

    // ---- per-stream pipeline ----
    for (int stream = 0; stream < 2; ++stream) {
        const float* x = stream == 0 ? h : g;
        const float* mT = stream == 0 ? pmTh : pmTg;
        float* dst = out + (size_t)stream * QB * DMODEL;

        // Q projection
        sgemm_nn<<<dim3(16, 64, 1), 256>>>(x, wq, pq, DMODEL, DMODEL, DMODEL, DMODEL, 0, 0, 0);
        // segment-term dot products
        compute_efq<<<(QLEN * BN_TOT + 255) / 256, 256>>>(pq, rsb, se, pe0, pe1);
        // S1[bn,i,j] = Q . K^T   (batched over bn)
        sgemm_nt<<<dim3(8, 8, BN_TOT), 256>>>(pq, pk, pS1, DHEAD,
                                              BN_TOT * DHEAD, BN_TOT * DHEAD, QLEN,
                                              DHEAD, DHEAD, (long long)QLEN * QLEN);
        // S2[bn,i,p] = Q . Kr^T
        sgemm_nt<<<dim3(16, 8, BN_TOT), 256>>>(pq, pkr, pS2, DHEAD,
                                               BN_TOT * DHEAD, BN_TOT * DHEAD, RLEN,
                                               DHEAD, DHEAD, (long long)QLEN * RLEN);
        // scores + rel-shift gather + seg + mask + softmax -> P (in S1)
        combine_softmax<<<dim3(QLEN, BN_TOT), 256>>>(pS1, pS2, pkbw, pkrb, pe0, pe1, mT, psegT);
        // attn_vec[i,b,n,d] = P . V  (batched over bn)
        sgemm_nn<<<dim3(1, 8, BN_TOT), 256>>>(pS1, pv, pav, QLEN,
                                              QLEN, BN_TOT * DHEAD, BN_TOT * DHEAD,
                                              (long long)QLEN * QLEN, DHEAD, DHEAD);
        // output projection: [4096,1024] @ wo[1024,1024]^T
        sgemm_nt<<<dim3(16, 64, 1), 256>>>(pav, wo, ptmp, DMODEL, DMODEL, DMODEL, DMODEL, 0, 0, 0);
        // residual + LayerNorm -> d_out
        residual_ln<<<QB, 256>>>(ptmp, x, gamma, beta, dst);
    }
    (void)in_sizes; (void)n_in; (void)out_size;
}